// round 1
// baseline (speedup 1.0000x reference)
#include <cuda_runtime.h>
#include <math.h>

// Problem constants
#define BB 4
#define SS 2048
#define DD 1024
#define HH 1024
#define SCALE 0.125f   // 64^-0.5

// Scratch (allocation-free rule: __device__ globals)
__device__ float g_q[BB * SS * HH];
__device__ float g_k[BB * SS * HH];
__device__ float g_v[BB * SS * HH];
__device__ float g_sc[BB * SS * SS];
__device__ float g_ctx[BB * SS * HH];

// ---------------------------------------------------------------------------
// Tiled SGEMM: C[z] = alpha * A[z] * op(B[z]) + bias
//   BT = true : C[m,n] = sum_k A[m,k] * B[n,k]   (B row-major [N,K], "NT")
//   BT = false: C[m,n] = sum_k A[m,k] * B[k,n]   (B row-major [K,N], "NN")
// All dims divisible by tile sizes (128/128/16) for this problem.
// ---------------------------------------------------------------------------
constexpr int BM = 128, BN = 128, BK = 16, TM = 8, TN = 8;

template <bool BT>
__global__ __launch_bounds__(256) void sgemm_kernel(
    const float* __restrict__ A, const float* __restrict__ Bm,
    const float* __restrict__ bias, float* __restrict__ C,
    int M, int N, int K, long sA, long sB, long sC, float alpha)
{
    A  += (long)blockIdx.z * sA;
    Bm += (long)blockIdx.z * sB;
    C  += (long)blockIdx.z * sC;

    __shared__ float As[BK][BM + 4];
    __shared__ float Bs[BK][BN + 4];

    const int tid = threadIdx.x;
    const int tx = tid & 15;       // 0..15 -> N direction
    const int ty = tid >> 4;       // 0..15 -> M direction
    const int rowBase = blockIdx.y * BM;
    const int colBase = blockIdx.x * BN;

    float acc[TM][TN] = {};

    for (int k0 = 0; k0 < K; k0 += BK) {
        // --- load A tile [BM x BK], store transposed As[BK][BM] ---
#pragma unroll
        for (int j = 0; j < 2; j++) {
            int idx = tid + j * 256;                 // 512 float4 total
            int r  = idx >> 2;                       // row in tile (0..127)
            int c4 = (idx & 3) * 4;                  // col in tile (0,4,8,12)
            float4 v = *reinterpret_cast<const float4*>(
                A + (long)(rowBase + r) * K + k0 + c4);
            As[c4 + 0][r] = v.x; As[c4 + 1][r] = v.y;
            As[c4 + 2][r] = v.z; As[c4 + 3][r] = v.w;
        }
        // --- load B tile ---
        if (BT) {
            // B row-major [N,K]; tile [BN x BK], store transposed Bs[BK][BN]
#pragma unroll
            for (int j = 0; j < 2; j++) {
                int idx = tid + j * 256;
                int r  = idx >> 2;
                int c4 = (idx & 3) * 4;
                float4 v = *reinterpret_cast<const float4*>(
                    Bm + (long)(colBase + r) * K + k0 + c4);
                Bs[c4 + 0][r] = v.x; Bs[c4 + 1][r] = v.y;
                Bs[c4 + 2][r] = v.z; Bs[c4 + 3][r] = v.w;
            }
        } else {
            // B row-major [K,N]; tile [BK x BN], direct store
#pragma unroll
            for (int j = 0; j < 2; j++) {
                int idx = tid + j * 256;
                int r  = idx >> 5;                   // 0..15
                int c4 = (idx & 31) * 4;             // 0..124
                float4 v = *reinterpret_cast<const float4*>(
                    Bm + (long)(k0 + r) * N + colBase + c4);
                *reinterpret_cast<float4*>(&Bs[r][c4]) = v;
            }
        }
        __syncthreads();

        // --- compute ---
#pragma unroll
        for (int kk = 0; kk < BK; kk++) {
            float a[TM], b[TN];
#pragma unroll
            for (int i = 0; i < TM; i++) a[i] = As[kk][ty * TM + i];
#pragma unroll
            for (int j = 0; j < TN; j++) b[j] = Bs[kk][tx * TN + j];
#pragma unroll
            for (int i = 0; i < TM; i++)
#pragma unroll
                for (int j = 0; j < TN; j++)
                    acc[i][j] += a[i] * b[j];
        }
        __syncthreads();
    }

    // --- epilogue: alpha scale + optional bias, float4 stores ---
#pragma unroll
    for (int i = 0; i < TM; i++) {
        long row = rowBase + ty * TM + i;
#pragma unroll
        for (int j = 0; j < TN; j += 4) {
            int col = colBase + tx * TN + j;
            float4 o;
            o.x = acc[i][j + 0] * alpha;
            o.y = acc[i][j + 1] * alpha;
            o.z = acc[i][j + 2] * alpha;
            o.w = acc[i][j + 3] * alpha;
            if (bias) {
                o.x += bias[col + 0];
                o.y += bias[col + 1];
                o.z += bias[col + 2];
                o.w += bias[col + 3];
            }
            *reinterpret_cast<float4*>(C + row * N + col) = o;
        }
    }
}

// ---------------------------------------------------------------------------
// Column softmax: softmax over the QUERY axis (axis=1 of [B, Sq, Sk]).
// scores stored row-major [Sq, Sk] per batch; one thread per column k.
// Accesses are fully coalesced across the thread dimension.
// ---------------------------------------------------------------------------
__global__ __launch_bounds__(256) void softmax_q_kernel(float* __restrict__ sc)
{
    const int k = blockIdx.x * 256 + threadIdx.x;
    float* p = sc + (long)blockIdx.y * SS * SS + k;

    float m = -INFINITY;
    for (int q = 0; q < SS; q++) {
        float v = p[(long)q * SS];
        m = fmaxf(m, v);
    }
    float sum = 0.f;
    for (int q = 0; q < SS; q++)
        sum += __expf(p[(long)q * SS] - m);
    float inv = 1.f / sum;
    for (int q = 0; q < SS; q++)
        p[(long)q * SS] = __expf(p[(long)q * SS] - m) * inv;
}

// ---------------------------------------------------------------------------

static float* sym_addr(const void* sym)
{
    void* p = nullptr;
    cudaGetSymbolAddress(&p, sym);
    return reinterpret_cast<float*>(p);
}

extern "C" void kernel_launch(void* const* d_in, const int* in_sizes, int n_in,
                              void* d_out, int out_size)
{
    const float* query = (const float*)d_in[0];
    const float* key   = (const float*)d_in[1];
    const float* value = (const float*)d_in[2];
    const float* Wq    = (const float*)d_in[3];
    const float* bq    = (const float*)d_in[4];
    const float* Wk    = (const float*)d_in[5];
    const float* bk    = (const float*)d_in[6];
    const float* Wv    = (const float*)d_in[7];
    const float* bv    = (const float*)d_in[8];
    const float* Wo    = (const float*)d_in[9];
    const float* bo    = (const float*)d_in[10];
    float* out = (float*)d_out;

    float* q   = sym_addr(g_q);
    float* kk  = sym_addr(g_k);
    float* v   = sym_addr(g_v);
    float* sc  = sym_addr(g_sc);
    float* ctx = sym_addr(g_ctx);

    const int M = BB * SS;   // 8192 rows for the projections

    dim3 blk(256);

    // 1) Projections: [B*S, D] x [H, D]^T -> [B*S, H]
    dim3 gproj(HH / BN, M / BM, 1);
    sgemm_kernel<true><<<gproj, blk>>>(query, Wq, bq, q,  M, HH, DD, 0, 0, 0, 1.0f);
    sgemm_kernel<true><<<gproj, blk>>>(key,   Wk, bk, kk, M, HH, DD, 0, 0, 0, 1.0f);
    sgemm_kernel<true><<<gproj, blk>>>(value, Wv, bv, v,  M, HH, DD, 0, 0, 0, 1.0f);

    // 2) Scores per batch: [S, H] x [S, H]^T -> [S, S], scaled
    dim3 gsc(SS / BN, SS / BM, BB);
    sgemm_kernel<true><<<gsc, blk>>>(q, kk, nullptr, sc, SS, SS, HH,
                                     (long)SS * HH, (long)SS * HH, (long)SS * SS,
                                     SCALE);

    // 3) Softmax over query axis (columns of the [Sq, Sk] matrix)
    dim3 gsm(SS / 256, BB);
    softmax_q_kernel<<<gsm, blk>>>(sc);

    // 4) Context per batch: [S, S] x [S, H] -> [S, H]   (NN)
    dim3 gctx(HH / BN, SS / BM, BB);
    sgemm_kernel<false><<<gctx, blk>>>(sc, v, nullptr, ctx, SS, HH, SS,
                                       (long)SS * SS, (long)SS * HH, (long)SS * HH,
                                       1.0f);

    // 5) Output projection: [B*S, H] x [D, H]^T + bo -> [B*S, D]
    dim3 gout(DD / BN, M / BM, 1);
    sgemm_kernel<true><<<gout, blk>>>(ctx, Wo, bo, out, M, DD, HH, 0, 0, 0, 1.0f);
}

// round 3
// speedup vs baseline: 2.6599x; 2.6599x over previous
#include <cuda_runtime.h>
#include <cuda_fp16.h>
#include <cstdint>
#include <math.h>

#define BB 4
#define SS 2048
#define DD 1024
#define HH 1024
#define SCALEF 0.125f

// ---------------- scratch (allocation-free rule) ----------------
__device__ float g_q[BB * SS * HH];
__device__ float g_k[BB * SS * HH];
__device__ float g_vT[BB * HH * SS];     // transposed V: [b][h][s]
__device__ float g_sc[BB * SS * SS];
__device__ float g_ctx[BB * SS * HH];
__device__ float g_pm[BB * 8 * SS];
__device__ float g_ps[BB * 8 * SS];
__device__ float g_colM[BB * SS];
__device__ float g_colI[BB * SS];

// ---------------- helpers ----------------
__device__ __forceinline__ uint32_t smem_u32(const void* p) {
    uint32_t a;
    asm("{ .reg .u64 t; cvta.to.shared.u64 t, %1; cvt.u32.u64 %0, t; }" : "=r"(a) : "l"(p));
    return a;
}

#define LDSM4(r, a) \
    asm volatile("ldmatrix.sync.aligned.m8n8.x4.shared.b16 {%0,%1,%2,%3}, [%4];" \
        : "=r"((r)[0]), "=r"((r)[1]), "=r"((r)[2]), "=r"((r)[3]) : "r"(a))

__device__ __forceinline__ void mma16816(float* c, const uint32_t* a, const uint32_t* b) {
    asm volatile("mma.sync.aligned.m16n8k16.row.col.f32.f16.f16.f32 "
        "{%0,%1,%2,%3}, {%4,%5,%6,%7}, {%8,%9}, {%0,%1,%2,%3};"
        : "+f"(c[0]), "+f"(c[1]), "+f"(c[2]), "+f"(c[3])
        : "r"(a[0]), "r"(a[1]), "r"(a[2]), "r"(a[3]), "r"(b[0]), "r"(b[1]));
}

// split fp32x4 into hi fp16x4 + lo fp16x4 (exact residual)
__device__ __forceinline__ void cvt_split(float4 v, uint32_t& h01, uint32_t& h23,
                                          uint32_t& l01, uint32_t& l23) {
    __half2 a = __floats2half2_rn(v.x, v.y);
    __half2 b = __floats2half2_rn(v.z, v.w);
    float r0 = v.x - __half2float(__low2half(a));
    float r1 = v.y - __half2float(__high2half(a));
    float r2 = v.z - __half2float(__low2half(b));
    float r3 = v.w - __half2float(__high2half(b));
    __half2 c = __floats2half2_rn(r0, r1);
    __half2 d = __floats2half2_rn(r2, r3);
    h01 = *reinterpret_cast<uint32_t*>(&a);
    h23 = *reinterpret_cast<uint32_t*>(&b);
    l01 = *reinterpret_cast<uint32_t*>(&c);
    l23 = *reinterpret_cast<uint32_t*>(&d);
}

// ---------------- HMMA split-fp16 NT GEMM ----------------
// C[m,n] = alpha * sum_k A[m,k] * B[n,k] (+ bias[n])
// tile 128x128, BK=32, 8 warps (2m x 4n), warp tile 64x32.
// smem rows padded to 40 halves (80B): gcd(5,8)=1 -> ldmatrix conflict-free.
#define LROW 80              // bytes per smem row
#define OFF_AL 10240
#define OFF_BH 20480
#define OFF_BL 30720
#define BUFSZ  40960
#define SMEM_SZ (2 * BUFSZ)

__global__ __launch_bounds__(256, 1) void gemm_hmma(
    const float* __restrict__ A, const float* __restrict__ B,
    const float* __restrict__ bias, float* __restrict__ C,
    int M, int N, int K, long sA, long sB, long sC, float alpha, int transV)
{
    extern __shared__ char smem[];
    const uint32_t sb = smem_u32(smem);
    const int tid  = threadIdx.x;
    const int lane = tid & 31;
    const int wid  = tid >> 5;
    const int wm   = wid & 1;       // 2 warps in m
    const int wn   = wid >> 1;      // 4 warps in n

    A += (long)blockIdx.z * sA;
    B += (long)blockIdx.z * sB;
    C += (long)blockIdx.z * sC;
    const int rowBase = blockIdx.y * 128;
    const int colBase = blockIdx.x * 128;

    const float* Ap = A + (long)rowBase * K;
    const float* Bp = B + (long)colBase * K;

    // per-thread load coords: 4 float4 for A, 4 for B per BK chunk
    const int ldRow = tid >> 3;           // base row (stride 32 per i)
    const int ldC4  = (tid & 7) << 2;     // fp32 col within chunk

    float acc[4][4][4] = {};
    float4 pa[4], pb[4];

    const int nch = K >> 5;

    // prologue: load chunk 0, convert, store to buffer 0
#pragma unroll
    for (int i = 0; i < 4; i++) {
        pa[i] = *reinterpret_cast<const float4*>(Ap + (long)(ldRow + i * 32) * K + ldC4);
        pb[i] = *reinterpret_cast<const float4*>(Bp + (long)(ldRow + i * 32) * K + ldC4);
    }
#pragma unroll
    for (int i = 0; i < 4; i++) {
        uint32_t h01, h23, l01, l23;
        int off = (ldRow + i * 32) * LROW + ldC4 * 2;
        cvt_split(pa[i], h01, h23, l01, l23);
        *reinterpret_cast<uint2*>(smem + off)          = make_uint2(h01, h23);
        *reinterpret_cast<uint2*>(smem + off + OFF_AL) = make_uint2(l01, l23);
        cvt_split(pb[i], h01, h23, l01, l23);
        *reinterpret_cast<uint2*>(smem + off + OFF_BH) = make_uint2(h01, h23);
        *reinterpret_cast<uint2*>(smem + off + OFF_BL) = make_uint2(l01, l23);
    }
    __syncthreads();

    for (int c = 0; c < nch; c++) {
        // prefetch next chunk into registers
        if (c + 1 < nch) {
            const int k0 = (c + 1) << 5;
#pragma unroll
            for (int i = 0; i < 4; i++) {
                pa[i] = *reinterpret_cast<const float4*>(Ap + (long)(ldRow + i * 32) * K + k0 + ldC4);
                pb[i] = *reinterpret_cast<const float4*>(Bp + (long)(ldRow + i * 32) * K + k0 + ldC4);
            }
        }

        // compute from buffer c&1
        const uint32_t base = sb + (c & 1) * BUFSZ;
#pragma unroll
        for (int ks = 0; ks < 2; ks++) {
            uint32_t ah[4][4], al[4][4], bh[2][4], bl[2][4];
            const int kcA = ks * 16 + ((lane >> 4) << 3);
            const int mr  = wm * 64 + (lane & 15);
#pragma unroll
            for (int mt = 0; mt < 4; mt++) {
                uint32_t ad = base + (mr + mt * 16) * LROW + kcA * 2;
                LDSM4(ah[mt], ad);
                LDSM4(al[mt], ad + OFF_AL);
            }
            const int nr  = wn * 32 + (lane & 7) + ((lane >> 4) << 3);
            const int kcB = ks * 16 + (((lane >> 3) & 1) << 3);
#pragma unroll
            for (int np = 0; np < 2; np++) {
                uint32_t bd = base + OFF_BH + (nr + np * 16) * LROW + kcB * 2;
                LDSM4(bh[np], bd);
                LDSM4(bl[np], bd + (OFF_BL - OFF_BH));
            }
#pragma unroll
            for (int mt = 0; mt < 4; mt++)
#pragma unroll
                for (int nt = 0; nt < 4; nt++) {
                    const uint32_t* fh = &bh[nt >> 1][(nt & 1) * 2];
                    const uint32_t* fl = &bl[nt >> 1][(nt & 1) * 2];
                    mma16816(acc[mt][nt], ah[mt], fh);   // hiA * hiB
                    mma16816(acc[mt][nt], ah[mt], fl);   // hiA * loB
                    mma16816(acc[mt][nt], al[mt], fh);   // loA * hiB
                }
        }

        // stage next chunk into the other buffer
        if (c + 1 < nch) {
            char* dst = smem + ((c + 1) & 1) * BUFSZ;
#pragma unroll
            for (int i = 0; i < 4; i++) {
                uint32_t h01, h23, l01, l23;
                int off = (ldRow + i * 32) * LROW + ldC4 * 2;
                cvt_split(pa[i], h01, h23, l01, l23);
                *reinterpret_cast<uint2*>(dst + off)          = make_uint2(h01, h23);
                *reinterpret_cast<uint2*>(dst + off + OFF_AL) = make_uint2(l01, l23);
                cvt_split(pb[i], h01, h23, l01, l23);
                *reinterpret_cast<uint2*>(dst + off + OFF_BH) = make_uint2(h01, h23);
                *reinterpret_cast<uint2*>(dst + off + OFF_BL) = make_uint2(l01, l23);
            }
            __syncthreads();
        }
    }

    // epilogue
#pragma unroll
    for (int mt = 0; mt < 4; mt++) {
        const int r0 = rowBase + wm * 64 + mt * 16 + (lane >> 2);
#pragma unroll
        for (int nt = 0; nt < 4; nt++) {
            const int c0 = colBase + wn * 32 + nt * 8 + (lane & 3) * 2;
            float v0 = acc[mt][nt][0] * alpha;
            float v1 = acc[mt][nt][1] * alpha;
            float v2 = acc[mt][nt][2] * alpha;
            float v3 = acc[mt][nt][3] * alpha;
            if (bias) {
                float b0 = __ldg(bias + c0), b1 = __ldg(bias + c0 + 1);
                v0 += b0; v1 += b1; v2 += b0; v3 += b1;
            }
            if (!transV) {
                *reinterpret_cast<float2*>(C + (long)r0 * N + c0)       = make_float2(v0, v1);
                *reinterpret_cast<float2*>(C + (long)(r0 + 8) * N + c0) = make_float2(v2, v3);
            } else {
                // scatter into vT layout [b][h][s]; rows index b*2048+s, cols index h
                const int b0i = r0 >> 11, s0 = r0 & 2047;
                const int b1i = (r0 + 8) >> 11, s1 = (r0 + 8) & 2047;
                float* t0 = C + (long)b0i * (HH * (long)SS) + s0;
                float* t1 = C + (long)b1i * (HH * (long)SS) + s1;
                t0[(long)c0 * SS] = v0;       t0[(long)(c0 + 1) * SS] = v1;
                t1[(long)c0 * SS] = v2;       t1[(long)(c0 + 1) * SS] = v3;
            }
        }
    }
}

// ---------------- split softmax over QUERY axis ----------------
__global__ __launch_bounds__(256) void softmax_part(const float* __restrict__ sc,
                                                    float* __restrict__ pm, float* __restrict__ ps)
{
    const int col = blockIdx.x * 256 + threadIdx.x;
    const int seg = blockIdx.y, b = blockIdx.z;
    const float* p = sc + (long)b * SS * SS + (long)seg * 256 * SS + col;
    float m = -INFINITY, s = 0.f;
#pragma unroll 4
    for (int r = 0; r < 256; r++) {
        float v = p[(long)r * SS];
        float nm = fmaxf(m, v);
        s = s * __expf(m - nm) + __expf(v - nm);
        m = nm;
    }
    pm[((long)b * 8 + seg) * SS + col] = m;
    ps[((long)b * 8 + seg) * SS + col] = s;
}

__global__ __launch_bounds__(256) void softmax_comb(const float* __restrict__ pm,
                                                    const float* __restrict__ ps,
                                                    float* __restrict__ cm, float* __restrict__ ci)
{
    const int i = blockIdx.x * 256 + threadIdx.x;   // b*SS + col
    const int b = i >> 11, col = i & 2047;
    float M = -INFINITY;
#pragma unroll
    for (int s = 0; s < 8; s++) M = fmaxf(M, pm[((long)b * 8 + s) * SS + col]);
    float S = 0.f;
#pragma unroll
    for (int s = 0; s < 8; s++)
        S += ps[((long)b * 8 + s) * SS + col] * __expf(pm[((long)b * 8 + s) * SS + col] - M);
    cm[i] = M;
    ci[i] = 1.f / S;
}

__global__ __launch_bounds__(256) void softmax_norm(float* __restrict__ sc,
                                                    const float* __restrict__ cm,
                                                    const float* __restrict__ ci)
{
    const long e = ((long)blockIdx.x * 256 + threadIdx.x) * 4;
    const int b = (int)(e >> 22);
    const int col = (int)(e & 2047);
    float4 v = *reinterpret_cast<float4*>(sc + e);
    float4 M = *reinterpret_cast<const float4*>(cm + (b << 11) + col);
    float4 I = *reinterpret_cast<const float4*>(ci + (b << 11) + col);
    v.x = __expf(v.x - M.x) * I.x;
    v.y = __expf(v.y - M.y) * I.y;
    v.z = __expf(v.z - M.z) * I.z;
    v.w = __expf(v.w - M.w) * I.w;
    *reinterpret_cast<float4*>(sc + e) = v;
}

// ---------------- launch ----------------
static float* sym_addr(const void* sym) {
    void* p = nullptr;
    cudaGetSymbolAddress(&p, sym);
    return reinterpret_cast<float*>(p);
}

extern "C" void kernel_launch(void* const* d_in, const int* in_sizes, int n_in,
                              void* d_out, int out_size)
{
    const float* query = (const float*)d_in[0];
    const float* key   = (const float*)d_in[1];
    const float* value = (const float*)d_in[2];
    const float* Wq    = (const float*)d_in[3];
    const float* bq    = (const float*)d_in[4];
    const float* Wk    = (const float*)d_in[5];
    const float* bk    = (const float*)d_in[6];
    const float* Wv    = (const float*)d_in[7];
    const float* bv    = (const float*)d_in[8];
    const float* Wo    = (const float*)d_in[9];
    const float* bo    = (const float*)d_in[10];
    float* out = (float*)d_out;

    float* q   = sym_addr(g_q);
    float* k   = sym_addr(g_k);
    float* vT  = sym_addr(g_vT);
    float* sc  = sym_addr(g_sc);
    float* ctx = sym_addr(g_ctx);
    float* pm  = sym_addr(g_pm);
    float* ps  = sym_addr(g_ps);
    float* cm  = sym_addr(g_colM);
    float* ci  = sym_addr(g_colI);

    cudaFuncSetAttribute(gemm_hmma, cudaFuncAttributeMaxDynamicSharedMemorySize, SMEM_SZ);

    const int M = BB * SS;   // 8192

    // 1) Projections: [8192,1024] x [1024,1024]^T
    dim3 gp(HH / 128, M / 128, 1);
    gemm_hmma<<<gp, 256, SMEM_SZ>>>(query, Wq, bq, q,  M, HH, DD, 0, 0, 0, 1.f, 0);
    gemm_hmma<<<gp, 256, SMEM_SZ>>>(key,   Wk, bk, k,  M, HH, DD, 0, 0, 0, 1.f, 0);
    gemm_hmma<<<gp, 256, SMEM_SZ>>>(value, Wv, bv, vT, M, HH, DD, 0, 0, 0, 1.f, 1);

    // 2) Scores per batch: [2048,1024] x [2048,1024]^T, *SCALE
    dim3 gs(SS / 128, SS / 128, BB);
    gemm_hmma<<<gs, 256, SMEM_SZ>>>(q, k, nullptr, sc, SS, SS, HH,
                                    (long)SS * HH, (long)SS * HH, (long)SS * SS, SCALEF, 0);

    // 3) Softmax over the query axis
    softmax_part<<<dim3(SS / 256, 8, BB), 256>>>(sc, pm, ps);
    softmax_comb<<<dim3(BB * SS / 256), 256>>>(pm, ps, cm, ci);
    softmax_norm<<<dim3(BB * SS * SS / 4 / 256), 256>>>(sc, cm, ci);

    // 4) Context: [2048,2048] x vT[1024,2048]^T per batch -> [2048,1024]
    dim3 gc(HH / 128, SS / 128, BB);
    gemm_hmma<<<gc, 256, SMEM_SZ>>>(sc, vT, nullptr, ctx, SS, HH, SS,
                                    (long)SS * SS, (long)HH * SS, (long)SS * HH, 1.f, 0);

    // 5) Output projection: [8192,1024] x [1024,1024]^T + bo
    dim3 go(DD / 128, M / 128, 1);
    gemm_hmma<<<go, 256, SMEM_SZ>>>(ctx, Wo, bo, out, M, DD, HH, 0, 0, 0, 1.f, 0);
}